// round 1
// baseline (speedup 1.0000x reference)
#include <cuda_runtime.h>

#define Bv 4
#define Tv 4096
#define Cv 1024
#define Hv 128
#define Mv (Bv*Tv)

#define BR 64
#define BC 64
#define NQB (Tv/BR)      // 64
#define NPAIR (NQB/2)    // 32

// Scratch for projected q,k,v (8 MB each)
__device__ float g_q[(size_t)Mv*Hv];
__device__ float g_k[(size_t)Mv*Hv];
__device__ float g_v[(size_t)Mv*Hv];

// ---------------------------------------------------------------------------
// Projection GEMM: out[m][h] = sum_c x[m][c] * W[c][h]
// Tile: BM=128, BN=128(=H), BK=16. 256 threads, 8x8 micro-tile per thread.
// grid.x = Mv/128 = 128, grid.y = 3 (q,k,v)
// ---------------------------------------------------------------------------
__global__ __launch_bounds__(256) void proj_kernel(
    const float* __restrict__ x,
    const float* __restrict__ Wq,
    const float* __restrict__ Wk,
    const float* __restrict__ Wv)
{
    __shared__ float Xs[128][20];   // [m][k], pad to 20 for bank spread + 16B align
    __shared__ float Ws[16][128];   // [k][h]

    const float* W;
    float* out;
    if (blockIdx.y == 0)      { W = Wq; out = g_q; }
    else if (blockIdx.y == 1) { W = Wk; out = g_k; }
    else                      { W = Wv; out = g_v; }

    const int m0  = blockIdx.x * 128;
    const int tid = threadIdx.x;
    const int tx  = tid & 15;
    const int ty  = tid >> 4;

    float acc[8][8];
    #pragma unroll
    for (int j = 0; j < 8; j++)
        #pragma unroll
        for (int n = 0; n < 8; n++) acc[j][n] = 0.f;

    for (int k0 = 0; k0 < Cv; k0 += 16) {
        // X tile: 128 rows x 16 cols = 512 float4
        #pragma unroll
        for (int i = 0; i < 2; i++) {
            int f = tid + i * 256;
            int m = f >> 2;
            int kk = (f & 3) * 4;
            float4 v = *(const float4*)&x[(size_t)(m0 + m) * Cv + k0 + kk];
            *(float4*)&Xs[m][kk] = v;
        }
        // W tile: 16 x 128 = 512 float4
        #pragma unroll
        for (int i = 0; i < 2; i++) {
            int f = tid + i * 256;
            int kk = f >> 5;
            int h = (f & 31) * 4;
            *(float4*)&Ws[kk][h] = *(const float4*)&W[(size_t)(k0 + kk) * Hv + h];
        }
        __syncthreads();

        #pragma unroll
        for (int kk = 0; kk < 16; kk++) {
            float a[8];
            #pragma unroll
            for (int j = 0; j < 4; j++) {
                a[j]     = Xs[ty * 4 + j][kk];
                a[4 + j] = Xs[64 + ty * 4 + j][kk];
            }
            float4 b0 = *(float4*)&Ws[kk][tx * 4];
            float4 b1 = *(float4*)&Ws[kk][64 + tx * 4];
            float b[8] = {b0.x, b0.y, b0.z, b0.w, b1.x, b1.y, b1.z, b1.w};
            #pragma unroll
            for (int j = 0; j < 8; j++)
                #pragma unroll
                for (int n = 0; n < 8; n++)
                    acc[j][n] += a[j] * b[n];
        }
        __syncthreads();
    }

    #pragma unroll
    for (int j = 0; j < 8; j++) {
        int r = (j < 4) ? (ty * 4 + j) : (64 + ty * 4 + (j - 4));
        size_t m = (size_t)(m0 + r);
        float4 o0 = make_float4(acc[j][0], acc[j][1], acc[j][2], acc[j][3]);
        float4 o1 = make_float4(acc[j][4], acc[j][5], acc[j][6], acc[j][7]);
        *(float4*)&out[m * Hv + tx * 4]      = o0;
        *(float4*)&out[m * Hv + 64 + tx * 4] = o1;
    }
}

// ---------------------------------------------------------------------------
// Flash attention, fp32, causal, NO 1/sqrt(H) scaling.
// BR=BC=64, 256 threads. Each CTA processes the q-block pair (p, NQB-1-p)
// => exactly NQB+1 = 65 k-block iterations per CTA (perfect balance).
// Smem (dynamic, 119808 B):
//   Qs [128][68]  (h-major transposed)
//   Ks [128][68]  (h-major transposed)
//   Vs [64][128]  (natural)
//   Pt [64][68]   (P transposed: [c][r])
// ---------------------------------------------------------------------------
#define QS_OFF 0
#define KS_OFF (128*68)
#define VS_OFF (2*128*68)
#define PT_OFF (2*128*68 + 64*128)
#define SMEM_FLOATS (2*128*68 + 64*128 + 64*68)
#define SMEM_BYTES (SMEM_FLOATS * 4)

__global__ __launch_bounds__(256, 1) void attn_kernel(float* __restrict__ out)
{
    extern __shared__ float sm[];
    float* Qs = sm + QS_OFF;
    float* Ks = sm + KS_OFF;
    float* Vs = sm + VS_OFF;
    float* Pt = sm + PT_OFF;

    const int tid = threadIdx.x;
    const int tx  = tid & 15;
    const int ty  = tid >> 4;
    const int b    = blockIdx.x / NPAIR;
    const int pair = blockIdx.x % NPAIR;

    #pragma unroll 1
    for (int sel = 0; sel < 2; sel++) {
        const int qb = sel ? (NQB - 1 - pair) : pair;

        __syncthreads();
        // Load Q tile transposed: Qs[h][r]
        {
            const float* qbase = g_q + (size_t)(b * Tv + qb * BR) * Hv;
            #pragma unroll
            for (int i = 0; i < 8; i++) {
                int f = tid + i * 256;
                int r = f & 63;
                int h0 = (f >> 6) * 4;
                float4 v = *(const float4*)&qbase[(size_t)r * Hv + h0];
                Qs[(h0 + 0) * 68 + r] = v.x;
                Qs[(h0 + 1) * 68 + r] = v.y;
                Qs[(h0 + 2) * 68 + r] = v.z;
                Qs[(h0 + 3) * 68 + r] = v.w;
            }
        }

        float o[4][8];
        float mprev[4], l[4];
        #pragma unroll
        for (int j = 0; j < 4; j++) {
            mprev[j] = -1e30f; l[j] = 0.f;
            #pragma unroll
            for (int n = 0; n < 8; n++) o[j][n] = 0.f;
        }
        __syncthreads();

        for (int jb = 0; jb <= qb; jb++) {
            const float* kbase = g_k + (size_t)(b * Tv + jb * BC) * Hv;
            const float* vbase = g_v + (size_t)(b * Tv + jb * BC) * Hv;
            // K tile transposed: Ks[h][c]
            #pragma unroll
            for (int i = 0; i < 8; i++) {
                int f = tid + i * 256;
                int r = f & 63;
                int h0 = (f >> 6) * 4;
                float4 v = *(const float4*)&kbase[(size_t)r * Hv + h0];
                Ks[(h0 + 0) * 68 + r] = v.x;
                Ks[(h0 + 1) * 68 + r] = v.y;
                Ks[(h0 + 2) * 68 + r] = v.z;
                Ks[(h0 + 3) * 68 + r] = v.w;
            }
            // V tile natural: Vs[c][h]
            #pragma unroll
            for (int i = 0; i < 8; i++) {
                int f = tid + i * 256;
                int c = f >> 5;
                int h0 = (f & 31) * 4;
                *(float4*)&Vs[c * 128 + h0] = *(const float4*)&vbase[(size_t)c * Hv + h0];
            }
            __syncthreads();

            // S = Q K^T, 4x4 per thread
            float s[4][4];
            #pragma unroll
            for (int j = 0; j < 4; j++)
                #pragma unroll
                for (int n = 0; n < 4; n++) s[j][n] = 0.f;

            #pragma unroll 4
            for (int h = 0; h < 128; h++) {
                float4 av = *(float4*)&Qs[h * 68 + ty * 4];
                float4 bv = *(float4*)&Ks[h * 68 + tx * 4];
                float a[4] = {av.x, av.y, av.z, av.w};
                float bb[4] = {bv.x, bv.y, bv.z, bv.w};
                #pragma unroll
                for (int j = 0; j < 4; j++)
                    #pragma unroll
                    for (int n = 0; n < 4; n++)
                        s[j][n] += a[j] * bb[n];
            }

            if (jb == qb) {
                #pragma unroll
                for (int j = 0; j < 4; j++)
                    #pragma unroll
                    for (int n = 0; n < 4; n++)
                        if (tx * 4 + n > ty * 4 + j) s[j][n] = -1e30f;
            }

            // Online softmax update per row
            #pragma unroll
            for (int j = 0; j < 4; j++) {
                float rmax = fmaxf(fmaxf(s[j][0], s[j][1]), fmaxf(s[j][2], s[j][3]));
                #pragma unroll
                for (int off = 8; off >= 1; off >>= 1)
                    rmax = fmaxf(rmax, __shfl_xor_sync(0xffffffffu, rmax, off));
                float mnew = fmaxf(mprev[j], rmax);
                float alpha = __expf(mprev[j] - mnew);
                float p0 = __expf(s[j][0] - mnew);
                float p1 = __expf(s[j][1] - mnew);
                float p2 = __expf(s[j][2] - mnew);
                float p3 = __expf(s[j][3] - mnew);
                float rsum = (p0 + p1) + (p2 + p3);
                #pragma unroll
                for (int off = 8; off >= 1; off >>= 1)
                    rsum += __shfl_xor_sync(0xffffffffu, rsum, off);
                l[j] = l[j] * alpha + rsum;
                mprev[j] = mnew;
                #pragma unroll
                for (int n = 0; n < 8; n++) o[j][n] *= alpha;
                s[j][0] = p0; s[j][1] = p1; s[j][2] = p2; s[j][3] = p3;
            }

            // Stage P transposed: Pt[c][r]
            #pragma unroll
            for (int n = 0; n < 4; n++) {
                int c = tx * 4 + n;
                *(float4*)&Pt[c * 68 + ty * 4] =
                    make_float4(s[0][n], s[1][n], s[2][n], s[3][n]);
            }
            __syncthreads();

            // O += P V
            #pragma unroll 2
            for (int c = 0; c < 64; c++) {
                float4 av = *(float4*)&Pt[c * 68 + ty * 4];
                float4 v0 = *(float4*)&Vs[c * 128 + tx * 4];
                float4 v1 = *(float4*)&Vs[c * 128 + 64 + tx * 4];
                float a[4] = {av.x, av.y, av.z, av.w};
                #pragma unroll
                for (int j = 0; j < 4; j++) {
                    o[j][0] += a[j] * v0.x;
                    o[j][1] += a[j] * v0.y;
                    o[j][2] += a[j] * v0.z;
                    o[j][3] += a[j] * v0.w;
                    o[j][4] += a[j] * v1.x;
                    o[j][5] += a[j] * v1.y;
                    o[j][6] += a[j] * v1.z;
                    o[j][7] += a[j] * v1.w;
                }
            }
            __syncthreads();
        }

        // Epilogue: normalize and store
        #pragma unroll
        for (int j = 0; j < 4; j++) {
            float inv = 1.0f / l[j];
            size_t row = (size_t)(b * Tv + qb * BR + ty * 4 + j);
            float4 o0 = make_float4(o[j][0] * inv, o[j][1] * inv, o[j][2] * inv, o[j][3] * inv);
            float4 o1 = make_float4(o[j][4] * inv, o[j][5] * inv, o[j][6] * inv, o[j][7] * inv);
            *(float4*)&out[row * Hv + tx * 4]      = o0;
            *(float4*)&out[row * Hv + 64 + tx * 4] = o1;
        }
    }
}

extern "C" void kernel_launch(void* const* d_in, const int* in_sizes, int n_in,
                              void* d_out, int out_size)
{
    const float* x  = (const float*)d_in[0];
    const float* Wq = (const float*)d_in[1];
    const float* Wk = (const float*)d_in[2];
    const float* Wv = (const float*)d_in[3];
    float* out = (float*)d_out;

    proj_kernel<<<dim3(Mv / 128, 3), 256>>>(x, Wq, Wk, Wv);

    cudaFuncSetAttribute(attn_kernel,
                         cudaFuncAttributeMaxDynamicSharedMemorySize, SMEM_BYTES);
    attn_kernel<<<Bv * NPAIR, 256, SMEM_BYTES>>>(out);
}

// round 6
// speedup vs baseline: 2.2818x; 2.2818x over previous
#include <cuda_runtime.h>
#include <cuda_bf16.h>
#include <cstdint>

#define Bv 4
#define Tv 4096
#define Cv 1024
#define Hv 128
#define Mv (Bv*Tv)

// bf16 hi/lo projected tensors
__device__ __nv_bfloat16 g_qhi[(size_t)Mv*Hv];
__device__ __nv_bfloat16 g_qlo[(size_t)Mv*Hv];
__device__ __nv_bfloat16 g_khi[(size_t)Mv*Hv];
__device__ __nv_bfloat16 g_klo[(size_t)Mv*Hv];
// V transposed: [h][m]  (m global token)
__device__ __nv_bfloat16 g_vThi[(size_t)Hv*Mv];
__device__ __nv_bfloat16 g_vTlo[(size_t)Hv*Mv];
// W hi/lo, K-major [o][h][c]
__device__ __nv_bfloat16 g_whi[3*(size_t)Hv*Cv];
__device__ __nv_bfloat16 g_wlo[3*(size_t)Hv*Cv];

// ---------------------------------------------------------------------------
__device__ __forceinline__ uint32_t smem_u32(const void* p) {
    uint32_t a;
    asm("{ .reg .u64 t; cvta.to.shared.u64 t, %1; cvt.u32.u64 %0, t; }"
        : "=r"(a) : "l"(p));
    return a;
}
#define SW128(off) ((off) ^ (((off) >> 3) & 0x70))

// pack two fp32 -> bf16x2 (e0 low, e1 high), round-to-nearest
__device__ __forceinline__ uint32_t packbf(float e0, float e1) {
    uint32_t r;
    asm("cvt.rn.bf16x2.f32 %0, %1, %2;" : "=r"(r) : "f"(e1), "f"(e0));
    return r;
}
__device__ __forceinline__ float bfres(float v) {
    return v - __bfloat162float(__float2bfloat16(v));
}

#define LDSM4(r0,r1,r2,r3,addr) \
    asm volatile("ldmatrix.sync.aligned.m8n8.x4.shared.b16 {%0,%1,%2,%3}, [%4];" \
                 : "=r"(r0),"=r"(r1),"=r"(r2),"=r"(r3) : "r"(addr))

#define MMA(d,a,b0,b1) \
    asm volatile("mma.sync.aligned.m16n8k16.row.col.f32.bf16.bf16.f32 " \
                 "{%0,%1,%2,%3},{%4,%5,%6,%7},{%8,%9},{%0,%1,%2,%3};" \
                 : "+f"((d)[0]),"+f"((d)[1]),"+f"((d)[2]),"+f"((d)[3]) \
                 : "r"((a)[0]),"r"((a)[1]),"r"((a)[2]),"r"((a)[3]), \
                   "r"(b0),"r"(b1))

// A-fragment (m16k16) smem address for this thread; tile rows are 128B wide.
__device__ __forceinline__ uint32_t a_addr(uint32_t base, int lane, int rowbase, int kb) {
    int row = rowbase + (lane & 15);
    int kk = kb + ((lane >> 4) << 4);
    return base + SW128(row * 128 + kk);
}
// B-fragment (n16 x k16) smem address
__device__ __forceinline__ uint32_t b_addr(uint32_t base, int lane, int nbase, int kb) {
    int n = nbase + (lane & 7) + ((lane >> 4) << 3);
    int kk = kb + ((lane >> 3) & 1) * 16;
    return base + SW128(n * 128 + kk);
}

// ---------------------------------------------------------------------------
// W fp32 [C][H] -> hi/lo bf16 K-major [o][H][C]
// ---------------------------------------------------------------------------
__global__ __launch_bounds__(256) void convert_w(
    const float* __restrict__ Wq, const float* __restrict__ Wk,
    const float* __restrict__ Wv)
{
    int id = blockIdx.x * 256 + threadIdx.x;     // 3*1024*128
    int o = id >> 17;
    int r = id & 131071;
    int h = r >> 10;
    int c = r & 1023;
    const float* W = (o == 0) ? Wq : (o == 1) ? Wk : Wv;
    float v = W[(size_t)c * Hv + h];
    __nv_bfloat16 hi = __float2bfloat16(v);
    __nv_bfloat16 lo = __float2bfloat16(v - __bfloat162float(hi));
    size_t oi = (size_t)o * Hv * Cv + (size_t)h * Cv + c;
    g_whi[oi] = hi;
    g_wlo[oi] = lo;
}

// ---------------------------------------------------------------------------
// Projection: out = x @ W via mma.sync bf16 hi/lo 3-term.
// grid (Mv/128, 3), 256 threads. CTA tile 128m x 128n, K-chunks of 64.
// smem: Xhi/Xlo [128][64], Whi/Wlo [128n][64k]  (4 x 16KB)
// Warp: wm=wid>>1 (32 rows), wn=wid&1 (64 cols).
// Epilogue: q/k -> bf16 hi/lo [m][h];  v -> bf16 hi/lo transposed [h][m].
// ---------------------------------------------------------------------------
#define PROJ_SMEM (4*16384 + 1024)

__global__ __launch_bounds__(256, 1) void proj_mma(const float* __restrict__ x)
{
    extern __shared__ char dsm[];
    uint32_t sb = (smem_u32(dsm) + 1023) & ~1023u;
    const uint32_t XHI = sb, XLO = sb + 16384, WHI = sb + 32768, WLO = sb + 49152;

    const int tid = threadIdx.x;
    const int wid = tid >> 5;
    const int l   = tid & 31;
    const int mt = blockIdx.x;
    const int o  = blockIdx.y;
    const int wm = wid >> 1;
    const int wn = wid & 1;

    const uint4* wh = (const uint4*)(g_whi + (size_t)o * Hv * Cv);
    const uint4* wl = (const uint4*)(g_wlo + (size_t)o * Hv * Cv);

    float acc[2][8][4];
    #pragma unroll
    for (int mi = 0; mi < 2; mi++)
        #pragma unroll
        for (int nf = 0; nf < 8; nf++)
            #pragma unroll
            for (int e = 0; e < 4; e++) acc[mi][nf][e] = 0.f;

    for (int c = 0; c < 16; c++) {
        // X tile: fp32 -> hi/lo bf16 in-register, store to smem
        #pragma unroll
        for (int i = 0; i < 8; i++) {
            int f = tid + i * 256;           // 0..2047
            int row = f >> 4;
            int c4 = f & 15;
            const float4 v = *(const float4*)&x[((size_t)(mt * 128 + row)) * Cv + c * 64 + c4 * 4];
            uint2 hi2 = make_uint2(packbf(v.x, v.y), packbf(v.z, v.w));
            uint2 lo2 = make_uint2(packbf(bfres(v.x), bfres(v.y)),
                                   packbf(bfres(v.z), bfres(v.w)));
            uint32_t off = SW128(row * 128 + c4 * 8);
            *(uint2*)(dsm + (XHI - smem_u32(dsm)) + off) = hi2;
            *(uint2*)(dsm + (XLO - smem_u32(dsm)) + off) = lo2;
        }
        // W tile: [128n][64k] bf16
        #pragma unroll
        for (int i = 0; i < 4; i++) {
            int f = tid + i * 256;           // 0..1023
            int n = f >> 3;
            int c8 = f & 7;
            uint4 vh = wh[(size_t)n * (Cv / 8) + c * 8 + c8];
            uint4 vl = wl[(size_t)n * (Cv / 8) + c * 8 + c8];
            uint32_t off = SW128(n * 128 + c8 * 16);
            *(uint4*)(dsm + (WHI - smem_u32(dsm)) + off) = vh;
            *(uint4*)(dsm + (WLO - smem_u32(dsm)) + off) = vl;
        }
        __syncthreads();

        #pragma unroll
        for (int kk = 0; kk < 4; kk++) {
            int kb = kk * 32;
            uint32_t ahi[2][4], alo[2][4];
            #pragma unroll
            for (int mi = 0; mi < 2; mi++) {
                LDSM4(ahi[mi][0], ahi[mi][1], ahi[mi][2], ahi[mi][3],
                      a_addr(XHI, l, wm * 32 + mi * 16, kb));
                LDSM4(alo[mi][0], alo[mi][1], alo[mi][2], alo[mi][3],
                      a_addr(XLO, l, wm * 32 + mi * 16, kb));
            }
            #pragma unroll
            for (int nf = 0; nf < 4; nf++) {
                uint32_t bh0, bh1, bh2, bh3, bl0, bl1, bl2, bl3;
                LDSM4(bh0, bh1, bh2, bh3, b_addr(WHI, l, wn * 64 + nf * 16, kb));
                LDSM4(bl0, bl1, bl2, bl3, b_addr(WLO, l, wn * 64 + nf * 16, kb));
                #pragma unroll
                for (int mi = 0; mi < 2; mi++) {
                    MMA(acc[mi][2*nf],   ahi[mi], bh0, bh1);
                    MMA(acc[mi][2*nf],   ahi[mi], bl0, bl1);
                    MMA(acc[mi][2*nf],   alo[mi], bh0, bh1);
                    MMA(acc[mi][2*nf+1], ahi[mi], bh2, bh3);
                    MMA(acc[mi][2*nf+1], ahi[mi], bl2, bl3);
                    MMA(acc[mi][2*nf+1], alo[mi], bh2, bh3);
                }
            }
        }
        __syncthreads();
    }

    // Epilogue
    __nv_bfloat16* dhi = (o == 0) ? g_qhi : g_khi;
    __nv_bfloat16* dlo = (o == 0) ? g_qlo : g_klo;
    #pragma unroll
    for (int mi = 0; mi < 2; mi++) {
        int rowA = mt * 128 + wm * 32 + mi * 16 + (l >> 2);
        int rowB = rowA + 8;
        #pragma unroll
        for (int nf = 0; nf < 8; nf++) {
            int col = wn * 64 + nf * 8 + (l & 3) * 2;
            float vA0 = acc[mi][nf][0], vA1 = acc[mi][nf][1];
            float vB0 = acc[mi][nf][2], vB1 = acc[mi][nf][3];
            if (o < 2) {
                *(uint32_t*)(dhi + (size_t)rowA * Hv + col) = packbf(vA0, vA1);
                *(uint32_t*)(dlo + (size_t)rowA * Hv + col) = packbf(bfres(vA0), bfres(vA1));
                *(uint32_t*)(dhi + (size_t)rowB * Hv + col) = packbf(vB0, vB1);
                *(uint32_t*)(dlo + (size_t)rowB * Hv + col) = packbf(bfres(vB0), bfres(vB1));
            } else {
                // transposed store [h][m]
                g_vThi[(size_t)(col    ) * Mv + rowA] = __float2bfloat16(vA0);
                g_vThi[(size_t)(col + 1) * Mv + rowA] = __float2bfloat16(vA1);
                g_vThi[(size_t)(col    ) * Mv + rowB] = __float2bfloat16(vB0);
                g_vThi[(size_t)(col + 1) * Mv + rowB] = __float2bfloat16(vB1);
                g_vTlo[(size_t)(col    ) * Mv + rowA] = __float2bfloat16(bfres(vA0));
                g_vTlo[(size_t)(col + 1) * Mv + rowA] = __float2bfloat16(bfres(vA1));
                g_vTlo[(size_t)(col    ) * Mv + rowB] = __float2bfloat16(bfres(vB0));
                g_vTlo[(size_t)(col + 1) * Mv + rowB] = __float2bfloat16(bfres(vB1));
            }
        }
    }
}

// ---------------------------------------------------------------------------
// Flash attention via mma.sync, BR=128, BC=64, 8 warps.
// Warp w owns rows [w*16, w*16+16) x all 64 cols of S => warp-local softmax.
// grid (32, 4) = (qb, b). kv iters jb = 0 .. 2*qb+1.
// smem: Qhi[2][128][64] Qlo | Khi[2][64][64] Klo | Vhi[128][64] Vlo  = 128KB
// ---------------------------------------------------------------------------
#define ATTN_SMEM (131072 + 1024)

__global__ __launch_bounds__(256, 1) void attn_mma(float* __restrict__ out)
{
    extern __shared__ char dsm[];
    uint32_t sb = (smem_u32(dsm) + 1023) & ~1023u;
    const uint32_t QHI = sb,            QLO = sb + 32768;
    const uint32_t KHI = sb + 65536,    KLO = sb + 81920;
    const uint32_t VHI = sb + 98304,    VLO = sb + 114688;
    char* dbase = dsm + (sb - smem_u32(dsm));

    const int tid = threadIdx.x;
    const int wid = tid >> 5;
    const int l   = tid & 31;
    const int qb = blockIdx.x;
    const int b  = blockIdx.y;

    // Load Q tile (128 rows x 128 h), split h into two 64-wide subtiles
    {
        const uint4* qh = (const uint4*)(g_qhi + ((size_t)b * Tv + qb * 128) * Hv);
        const uint4* ql = (const uint4*)(g_qlo + ((size_t)b * Tv + qb * 128) * Hv);
        #pragma unroll
        for (int i = 0; i < 8; i++) {
            int f = tid + i * 256;       // 0..2047
            int row = f >> 4;
            int c = f & 15;
            int hh = c >> 3, hl = c & 7;
            uint32_t off = hh * 16384 + SW128(row * 128 + hl * 16);
            *(uint4*)(dbase + (QHI - sb) + off) = qh[(size_t)row * 16 + c];
            *(uint4*)(dbase + (QLO - sb) + off) = ql[(size_t)row * 16 + c];
        }
    }

    float o_acc[16][4];
    #pragma unroll
    for (int f = 0; f < 16; f++)
        #pragma unroll
        for (int e = 0; e < 4; e++) o_acc[f][e] = 0.f;
    float mA = -1e30f, mB = -1e30f, lA = 0.f, lB = 0.f;

    const int jbmax = 2 * qb + 1;
    for (int jb = 0; jb <= jbmax; jb++) {
        // Load K tile (64 x 128h -> [2][64][64]) and V tile ([128h][64m])
        {
            const uint4* kh = (const uint4*)(g_khi + ((size_t)b * Tv + jb * 64) * Hv);
            const uint4* kl = (const uint4*)(g_klo + ((size_t)b * Tv + jb * 64) * Hv);
            #pragma unroll
            for (int i = 0; i < 4; i++) {
                int f = tid + i * 256;   // 0..1023
                int row = f >> 4;
                int c = f & 15;
                int hh = c >> 3, hl = c & 7;
                uint32_t off = hh * 8192 + SW128(row * 128 + hl * 16);
                *(uint4*)(dbase + (KHI - sb) + off) = kh[(size_t)row * 16 + c];
                *(uint4*)(dbase + (KLO - sb) + off) = kl[(size_t)row * 16 + c];
            }
            size_t vbo = ((size_t)b * Tv + jb * 64) / 8;
            const uint4* vh = (const uint4*)g_vThi;
            const uint4* vl = (const uint4*)g_vTlo;
            #pragma unroll
            for (int i = 0; i < 4; i++) {
                int f = tid + i * 256;   // 0..1023
                int h = f >> 3;
                int c = f & 7;
                uint32_t off = SW128(h * 128 + c * 16);
                *(uint4*)(dbase + (VHI - sb) + off) = vh[(size_t)h * (Mv / 8) + vbo + c];
                *(uint4*)(dbase + (VLO - sb) + off) = vl[(size_t)h * (Mv / 8) + vbo + c];
            }
        }
        __syncthreads();

        // S = Q K^T  (warp tile 16 x 64)
        float s[8][4];
        #pragma unroll
        for (int f = 0; f < 8; f++)
            #pragma unroll
            for (int e = 0; e < 4; e++) s[f][e] = 0.f;

        #pragma unroll
        for (int kk = 0; kk < 8; kk++) {
            int hh = kk >> 2;
            int kb = (kk & 3) * 32;
            uint32_t ahi[4], alo[4];
            LDSM4(ahi[0], ahi[1], ahi[2], ahi[3],
                  a_addr(QHI + hh * 16384, l, wid * 16, kb));
            LDSM4(alo[0], alo[1], alo[2], alo[3],
                  a_addr(QLO + hh * 16384, l, wid * 16, kb));
            #pragma unroll
            for (int nf = 0; nf < 4; nf++) {
                uint32_t bh0, bh1, bh2, bh3, bl0, bl1, bl2, bl3;
                LDSM4(bh0, bh1, bh2, bh3, b_addr(KHI + hh * 8192, l, nf * 16, kb));
                LDSM4(bl0, bl1, bl2, bl3, b_addr(KLO + hh * 8192, l, nf * 16, kb));
                MMA(s[2*nf],   ahi, bh0, bh1);
                MMA(s[2*nf],   ahi, bl0, bl1);
                MMA(s[2*nf],   alo, bh0, bh1);
                MMA(s[2*nf+1], ahi, bh2, bh3);
                MMA(s[2*nf+1], ahi, bl2, bl3);
                MMA(s[2*nf+1], alo, bh2, bh3);
            }
        }

        // Causal mask on diagonal blocks
        if (jb >= 2 * qb) {
            int rbase = qb * 128 + wid * 16 + (l >> 2);
            int cbase = jb * 64 + (l & 3) * 2;
            #pragma unroll
            for (int f = 0; f < 8; f++) {
                int c0 = cbase + f * 8;
                if (c0     > rbase)     s[f][0] = -1e30f;
                if (c0 + 1 > rbase)     s[f][1] = -1e30f;
                if (c0     > rbase + 8) s[f][2] = -1e30f;
                if (c0 + 1 > rbase + 8) s[f][3] = -1e30f;
            }
        }

        // Online softmax (rows l>>2 and l>>2+8; reduce over lanes l^1, l^2)
        float rmA = -1e30f, rmB = -1e30f;
        #pragma unroll
        for (int f = 0; f < 8; f++) {
            rmA = fmaxf(rmA, fmaxf(s[f][0], s[f][1]));
            rmB = fmaxf(rmB, fmaxf(s[f][2], s[f][3]));
        }
        rmA = fmaxf(rmA, __shfl_xor_sync(0xffffffffu, rmA, 1));
        rmA = fmaxf(rmA, __shfl_xor_sync(0xffffffffu, rmA, 2));
        rmB = fmaxf(rmB, __shfl_xor_sync(0xffffffffu, rmB, 1));
        rmB = fmaxf(rmB, __shfl_xor_sync(0xffffffffu, rmB, 2));
        float mnA = fmaxf(mA, rmA), mnB = fmaxf(mB, rmB);
        float aA = __expf(mA - mnA), aB = __expf(mB - mnB);
        float sumA = 0.f, sumB = 0.f;
        #pragma unroll
        for (int f = 0; f < 8; f++) {
            s[f][0] = __expf(s[f][0] - mnA);
            s[f][1] = __expf(s[f][1] - mnA);
            s[f][2] = __expf(s[f][2] - mnB);
            s[f][3] = __expf(s[f][3] - mnB);
            sumA += s[f][0] + s[f][1];
            sumB += s[f][2] + s[f][3];
        }
        sumA += __shfl_xor_sync(0xffffffffu, sumA, 1);
        sumA += __shfl_xor_sync(0xffffffffu, sumA, 2);
        sumB += __shfl_xor_sync(0xffffffffu, sumB, 1);
        sumB += __shfl_xor_sync(0xffffffffu, sumB, 2);
        lA = lA * aA + sumA; mA = mnA;
        lB = lB * aB + sumB; mB = mnB;
        #pragma unroll
        for (int f = 0; f < 16; f++) {
            o_acc[f][0] *= aA; o_acc[f][1] *= aA;
            o_acc[f][2] *= aB; o_acc[f][3] *= aB;
        }

        // P fragments (A-layout == accum layout, no shuffles)
        uint32_t ph[4][4], pl[4][4];
        #pragma unroll
        for (int kk = 0; kk < 4; kk++) {
            int f0 = 2 * kk, f1 = 2 * kk + 1;
            ph[kk][0] = packbf(s[f0][0], s[f0][1]);
            ph[kk][1] = packbf(s[f0][2], s[f0][3]);
            ph[kk][2] = packbf(s[f1][0], s[f1][1]);
            ph[kk][3] = packbf(s[f1][2], s[f1][3]);
            pl[kk][0] = packbf(bfres(s[f0][0]), bfres(s[f0][1]));
            pl[kk][1] = packbf(bfres(s[f0][2]), bfres(s[f0][3]));
            pl[kk][2] = packbf(bfres(s[f1][0]), bfres(s[f1][1]));
            pl[kk][3] = packbf(bfres(s[f1][2]), bfres(s[f1][3]));
        }

        // O += P V  (n = h = 128, k = 64)
        #pragma unroll
        for (int kk = 0; kk < 4; kk++) {
            int kb = kk * 32;
            #pragma unroll
            for (int nf = 0; nf < 8; nf++) {
                uint32_t vh0, vh1, vh2, vh3, vl0, vl1, vl2, vl3;
                LDSM4(vh0, vh1, vh2, vh3, b_addr(VHI, l, nf * 16, kb));
                LDSM4(vl0, vl1, vl2, vl3, b_addr(VLO, l, nf * 16, kb));
                MMA(o_acc[2*nf],   ph[kk], vh0, vh1);
                MMA(o_acc[2*nf],   ph[kk], vl0, vl1);
                MMA(o_acc[2*nf],   pl[kk], vh0, vh1);
                MMA(o_acc[2*nf+1], ph[kk], vh2, vh3);
                MMA(o_acc[2*nf+1], ph[kk], vl2, vl3);
                MMA(o_acc[2*nf+1], pl[kk], vh2, vh3);
            }
        }
        __syncthreads();
    }

    // Epilogue
    float iA = 1.f / lA, iB = 1.f / lB;
    size_t rowA = (size_t)b * Tv + qb * 128 + wid * 16 + (l >> 2);
    size_t rowB = rowA + 8;
    #pragma unroll
    for (int f = 0; f < 16; f++) {
        int h = f * 8 + (l & 3) * 2;
        *(float2*)&out[rowA * Hv + h] = make_float2(o_acc[f][0] * iA, o_acc[f][1] * iA);
        *(float2*)&out[rowB * Hv + h] = make_float2(o_acc[f][2] * iB, o_acc[f][3] * iB);
    }
}

extern "C" void kernel_launch(void* const* d_in, const int* in_sizes, int n_in,
                              void* d_out, int out_size)
{
    const float* x  = (const float*)d_in[0];
    const float* Wq = (const float*)d_in[1];
    const float* Wk = (const float*)d_in[2];
    const float* Wv = (const float*)d_in[3];
    float* out = (float*)d_out;

    convert_w<<<(3 * Cv * Hv) / 256, 256>>>(Wq, Wk, Wv);

    cudaFuncSetAttribute(proj_mma,
                         cudaFuncAttributeMaxDynamicSharedMemorySize, PROJ_SMEM);
    proj_mma<<<dim3(Mv / 128, 3), 256, PROJ_SMEM>>>(x);

    cudaFuncSetAttribute(attn_mma,
                         cudaFuncAttributeMaxDynamicSharedMemorySize, ATTN_SMEM);
    attn_mma<<<dim3(32, Bv), 256, ATTN_SMEM>>>(out);
}

// round 8
// speedup vs baseline: 2.7426x; 1.2019x over previous
#include <cuda_runtime.h>
#include <cuda_bf16.h>
#include <cstdint>

#define Bv 4
#define Tv 4096
#define Cv 1024
#define Hv 128
#define Mv (Bv*Tv)

// bf16 hi/lo projected tensors
__device__ __nv_bfloat16 g_qhi[(size_t)Mv*Hv];
__device__ __nv_bfloat16 g_qlo[(size_t)Mv*Hv];
__device__ __nv_bfloat16 g_khi[(size_t)Mv*Hv];
__device__ __nv_bfloat16 g_klo[(size_t)Mv*Hv];
// V transposed: [h][m]
__device__ __nv_bfloat16 g_vThi[(size_t)Hv*Mv];
__device__ __nv_bfloat16 g_vTlo[(size_t)Hv*Mv];
// W hi/lo, K-major [o][h][c]
__device__ __nv_bfloat16 g_whi[3*(size_t)Hv*Cv];
__device__ __nv_bfloat16 g_wlo[3*(size_t)Hv*Cv];

// ---------------------------------------------------------------------------
__device__ __forceinline__ uint32_t smem_u32(const void* p) {
    uint32_t a;
    asm("{ .reg .u64 t; cvta.to.shared.u64 t, %1; cvt.u32.u64 %0, t; }"
        : "=r"(a) : "l"(p));
    return a;
}
#define SW128(off) ((off) ^ (((off) >> 3) & 0x70))

__device__ __forceinline__ uint32_t packbf(float e0, float e1) {
    uint32_t r;
    asm("cvt.rn.bf16x2.f32 %0, %1, %2;" : "=r"(r) : "f"(e1), "f"(e0));
    return r;
}
__device__ __forceinline__ float bfres(float v) {
    return v - __bfloat162float(__float2bfloat16(v));
}

#define LDSM4(r0,r1,r2,r3,addr) \
    asm volatile("ldmatrix.sync.aligned.m8n8.x4.shared.b16 {%0,%1,%2,%3}, [%4];" \
                 : "=r"(r0),"=r"(r1),"=r"(r2),"=r"(r3) : "r"(addr))

#define MMA(d,a,b0,b1) \
    asm volatile("mma.sync.aligned.m16n8k16.row.col.f32.bf16.bf16.f32 " \
                 "{%0,%1,%2,%3},{%4,%5,%6,%7},{%8,%9},{%0,%1,%2,%3};" \
                 : "+f"((d)[0]),"+f"((d)[1]),"+f"((d)[2]),"+f"((d)[3]) \
                 : "r"((a)[0]),"r"((a)[1]),"r"((a)[2]),"r"((a)[3]), \
                   "r"(b0),"r"(b1))

#define CP16(dst_u32, src_ptr) \
    asm volatile("cp.async.cg.shared.global [%0], [%1], 16;" \
                 :: "r"(dst_u32), "l"(src_ptr) : "memory")
#define CP_COMMIT() asm volatile("cp.async.commit_group;" ::: "memory")
#define CP_WAIT1()  asm volatile("cp.async.wait_group 1;" ::: "memory")

__device__ __forceinline__ uint32_t a_addr(uint32_t base, int lane, int rowbase, int kb) {
    int row = rowbase + (lane & 15);
    int kk = kb + ((lane >> 4) << 4);
    return base + SW128(row * 128 + kk);
}
__device__ __forceinline__ uint32_t b_addr(uint32_t base, int lane, int nbase, int kb) {
    int n = nbase + (lane & 7) + ((lane >> 4) << 3);
    int kk = kb + ((lane >> 3) & 1) * 16;
    return base + SW128(n * 128 + kk);
}

// ---------------------------------------------------------------------------
__global__ __launch_bounds__(256) void convert_w(
    const float* __restrict__ Wq, const float* __restrict__ Wk,
    const float* __restrict__ Wv)
{
    int id = blockIdx.x * 256 + threadIdx.x;
    int o = id >> 17;
    int r = id & 131071;
    int h = r >> 10;
    int c = r & 1023;
    const float* W = (o == 0) ? Wq : (o == 1) ? Wk : Wv;
    float v = W[(size_t)c * Hv + h];
    __nv_bfloat16 hi = __float2bfloat16(v);
    __nv_bfloat16 lo = __float2bfloat16(v - __bfloat162float(hi));
    size_t oi = (size_t)o * Hv * Cv + (size_t)h * Cv + c;
    g_whi[oi] = hi;
    g_wlo[oi] = lo;
}

// ---------------------------------------------------------------------------
// Projection, double-buffered pipeline.
// buf b at sb + b*65536: XHI +0, XLO +16384, WHI +32768, WLO +49152
// ---------------------------------------------------------------------------
#define PROJ_SMEM (2*65536 + 1024)

__global__ __launch_bounds__(256, 1) void proj_mma(const float* __restrict__ x)
{
    extern __shared__ char dsm[];
    uint32_t sb = (smem_u32(dsm) + 1023) & ~1023u;
    char* p0 = dsm + (sb - smem_u32(dsm));

    const int tid = threadIdx.x;
    const int wid = tid >> 5;
    const int l   = tid & 31;
    const int mt = blockIdx.x;
    const int o  = blockIdx.y;
    const int wm = wid >> 1;
    const int wn = wid & 1;

    const uint4* wh = (const uint4*)(g_whi + (size_t)o * Hv * Cv);
    const uint4* wl = (const uint4*)(g_wlo + (size_t)o * Hv * Cv);

    // per-thread load coords
    const int xrow[8] = { (tid)>>4, (tid+256)>>4, (tid+512)>>4, (tid+768)>>4,
                          (tid+1024)>>4, (tid+1280)>>4, (tid+1536)>>4, (tid+1792)>>4 };
    const int xc4 = tid & 15;

    float acc[2][8][4];
    #pragma unroll
    for (int mi = 0; mi < 2; mi++)
        #pragma unroll
        for (int nf = 0; nf < 8; nf++)
            #pragma unroll
            for (int e = 0; e < 4; e++) acc[mi][nf][e] = 0.f;

    // W cp.async issue for chunk c into buffer base
    auto issue_w = [&](int c, uint32_t bufb) {
        #pragma unroll
        for (int i = 0; i < 4; i++) {
            int f = tid + i * 256;
            int n = f >> 3;
            int c8 = f & 7;
            uint32_t off = SW128(n * 128 + c8 * 16);
            CP16(bufb + 32768 + off, wh + (size_t)n * 128 + c * 8 + c8);
            CP16(bufb + 49152 + off, wl + (size_t)n * 128 + c * 8 + c8);
        }
    };
    auto ldg_x = [&](int c, float4* xp) {
        #pragma unroll
        for (int i = 0; i < 8; i++)
            xp[i] = *(const float4*)&x[((size_t)(mt * 128 + xrow[i])) * Cv + c * 64 + xc4 * 4];
    };
    auto sts_x = [&](const float4* xp, char* bufp) {
        #pragma unroll
        for (int i = 0; i < 8; i++) {
            float4 v = xp[i];
            uint2 hi2 = make_uint2(packbf(v.x, v.y), packbf(v.z, v.w));
            uint2 lo2 = make_uint2(packbf(bfres(v.x), bfres(v.y)),
                                   packbf(bfres(v.z), bfres(v.w)));
            uint32_t off = SW128(xrow[i] * 128 + xc4 * 8);
            *(uint2*)(bufp + off) = hi2;
            *(uint2*)(bufp + 16384 + off) = lo2;
        }
    };

    // prologue: chunk 0
    {
        float4 xp[8];
        ldg_x(0, xp);
        issue_w(0, sb);
        CP_COMMIT();
        sts_x(xp, p0);
    }

    for (int c = 0; c < 16; c++) {
        int cb = c & 1;
        uint32_t curb = sb + cb * 65536;
        char* curp = p0 + cb * 65536;
        uint32_t nxtb = sb + (cb ^ 1) * 65536;
        char* nxtp = p0 + (cb ^ 1) * 65536;

        float4 xp[8];
        if (c < 15) {
            ldg_x(c + 1, xp);
            issue_w(c + 1, nxtb);
        }
        CP_COMMIT();
        CP_WAIT1();
        __syncthreads();

        const uint32_t XHI = curb, XLO = curb + 16384;
        const uint32_t WHI = curb + 32768, WLO = curb + 49152;
        #pragma unroll
        for (int kk = 0; kk < 4; kk++) {
            int kb = kk * 32;
            uint32_t ahi[2][4], alo[2][4];
            #pragma unroll
            for (int mi = 0; mi < 2; mi++) {
                LDSM4(ahi[mi][0], ahi[mi][1], ahi[mi][2], ahi[mi][3],
                      a_addr(XHI, l, wm * 32 + mi * 16, kb));
                LDSM4(alo[mi][0], alo[mi][1], alo[mi][2], alo[mi][3],
                      a_addr(XLO, l, wm * 32 + mi * 16, kb));
            }
            #pragma unroll
            for (int nf = 0; nf < 4; nf++) {
                uint32_t bh0, bh1, bh2, bh3, bl0, bl1, bl2, bl3;
                LDSM4(bh0, bh1, bh2, bh3, b_addr(WHI, l, wn * 64 + nf * 16, kb));
                LDSM4(bl0, bl1, bl2, bl3, b_addr(WLO, l, wn * 64 + nf * 16, kb));
                #pragma unroll
                for (int mi = 0; mi < 2; mi++) {
                    MMA(acc[mi][2*nf],   ahi[mi], bh0, bh1);
                    MMA(acc[mi][2*nf],   ahi[mi], bl0, bl1);
                    MMA(acc[mi][2*nf],   alo[mi], bh0, bh1);
                    MMA(acc[mi][2*nf+1], ahi[mi], bh2, bh3);
                    MMA(acc[mi][2*nf+1], ahi[mi], bl2, bl3);
                    MMA(acc[mi][2*nf+1], alo[mi], bh2, bh3);
                }
            }
        }
        if (c < 15) sts_x(xp, nxtp);
        __syncthreads();
    }

    // Epilogue
    __nv_bfloat16* dhi = (o == 0) ? g_qhi : g_khi;
    __nv_bfloat16* dlo = (o == 0) ? g_qlo : g_klo;
    #pragma unroll
    for (int mi = 0; mi < 2; mi++) {
        int rowA = mt * 128 + wm * 32 + mi * 16 + (l >> 2);
        int rowB = rowA + 8;
        #pragma unroll
        for (int nf = 0; nf < 8; nf++) {
            int col = wn * 64 + nf * 8 + (l & 3) * 2;
            float vA0 = acc[mi][nf][0], vA1 = acc[mi][nf][1];
            float vB0 = acc[mi][nf][2], vB1 = acc[mi][nf][3];
            if (o < 2) {
                *(uint32_t*)(dhi + (size_t)rowA * Hv + col) = packbf(vA0, vA1);
                *(uint32_t*)(dlo + (size_t)rowA * Hv + col) = packbf(bfres(vA0), bfres(vA1));
                *(uint32_t*)(dhi + (size_t)rowB * Hv + col) = packbf(vB0, vB1);
                *(uint32_t*)(dlo + (size_t)rowB * Hv + col) = packbf(bfres(vB0), bfres(vB1));
            } else {
                g_vThi[(size_t)(col    ) * Mv + rowA] = __float2bfloat16(vA0);
                g_vThi[(size_t)(col + 1) * Mv + rowA] = __float2bfloat16(vA1);
                g_vThi[(size_t)(col    ) * Mv + rowB] = __float2bfloat16(vB0);
                g_vThi[(size_t)(col + 1) * Mv + rowB] = __float2bfloat16(vB1);
                g_vTlo[(size_t)(col    ) * Mv + rowA] = __float2bfloat16(bfres(vA0));
                g_vTlo[(size_t)(col + 1) * Mv + rowA] = __float2bfloat16(bfres(vA1));
                g_vTlo[(size_t)(col    ) * Mv + rowB] = __float2bfloat16(bfres(vB0));
                g_vTlo[(size_t)(col + 1) * Mv + rowB] = __float2bfloat16(bfres(vB1));
            }
        }
    }
}

// ---------------------------------------------------------------------------
// Flash attention, cp.async double-buffered K/V.
// Q: QHI sb+0 (32KB), QLO sb+32768.
// KV buffer b at sb+65536+b*65536: KHI +0, KLO +16384, VHI +32768, VLO +49152
// ---------------------------------------------------------------------------
#define ATTN_SMEM (65536 + 2*65536 + 1024)

__global__ __launch_bounds__(256, 1) void attn_mma(float* __restrict__ out)
{
    extern __shared__ char dsm[];
    uint32_t sb = (smem_u32(dsm) + 1023) & ~1023u;
    char* p0 = dsm + (sb - smem_u32(dsm));
    const uint32_t QHI = sb, QLO = sb + 32768;

    const int tid = threadIdx.x;
    const int wid = tid >> 5;
    const int l   = tid & 31;
    const int qb = blockIdx.x;
    const int b  = blockIdx.y;

    const uint4* vh = (const uint4*)g_vThi;
    const uint4* vl = (const uint4*)g_vTlo;

    // issue cp.async K/V loads for block jb into buffer base
    auto issue_kv = [&](int jb, uint32_t bufb) {
        const uint4* kh = (const uint4*)(g_khi + ((size_t)b * Tv + jb * 64) * Hv);
        const uint4* kl = (const uint4*)(g_klo + ((size_t)b * Tv + jb * 64) * Hv);
        #pragma unroll
        for (int i = 0; i < 4; i++) {
            int f = tid + i * 256;
            int row = f >> 4;
            int c = f & 15;
            int hh = c >> 3, hl = c & 7;
            uint32_t off = hh * 8192 + SW128(row * 128 + hl * 16);
            CP16(bufb + off,         kh + (size_t)row * 16 + c);
            CP16(bufb + 16384 + off, kl + (size_t)row * 16 + c);
        }
        size_t vbo = ((size_t)b * Tv + jb * 64) / 8;
        #pragma unroll
        for (int i = 0; i < 4; i++) {
            int f = tid + i * 256;
            int h = f >> 3;
            int c = f & 7;
            uint32_t off = SW128(h * 128 + c * 16);
            CP16(bufb + 32768 + off, vh + (size_t)h * (Mv / 8) + vbo + c);
            CP16(bufb + 49152 + off, vl + (size_t)h * (Mv / 8) + vbo + c);
        }
    };

    // prologue: KV(0) + Q
    issue_kv(0, sb + 65536);
    CP_COMMIT();
    {
        const uint4* qh = (const uint4*)(g_qhi + ((size_t)b * Tv + qb * 128) * Hv);
        const uint4* ql = (const uint4*)(g_qlo + ((size_t)b * Tv + qb * 128) * Hv);
        #pragma unroll
        for (int i = 0; i < 8; i++) {
            int f = tid + i * 256;
            int row = f >> 4;
            int c = f & 15;
            int hh = c >> 3, hl = c & 7;
            uint32_t off = hh * 16384 + SW128(row * 128 + hl * 16);
            *(uint4*)(p0 + off)         = qh[(size_t)row * 16 + c];
            *(uint4*)(p0 + 32768 + off) = ql[(size_t)row * 16 + c];
        }
    }

    float o_acc[16][4];
    #pragma unroll
    for (int f = 0; f < 16; f++)
        #pragma unroll
        for (int e = 0; e < 4; e++) o_acc[f][e] = 0.f;
    float mA = -1e30f, mB = -1e30f, lA = 0.f, lB = 0.f;

    const int jbmax = 2 * qb + 1;
    for (int jb = 0; jb <= jbmax; jb++) {
        uint32_t curb = sb + 65536 + (jb & 1) * 65536;
        if (jb < jbmax) issue_kv(jb + 1, sb + 65536 + ((jb + 1) & 1) * 65536);
        CP_COMMIT();
        CP_WAIT1();
        __syncthreads();

        const uint32_t KHI = curb, KLO = curb + 16384;
        const uint32_t VHI = curb + 32768, VLO = curb + 49152;

        // S = Q K^T
        float s[8][4];
        #pragma unroll
        for (int f = 0; f < 8; f++)
            #pragma unroll
            for (int e = 0; e < 4; e++) s[f][e] = 0.f;

        #pragma unroll
        for (int kk = 0; kk < 8; kk++) {
            int hh = kk >> 2;
            int kb = (kk & 3) * 32;
            uint32_t ahi[4], alo[4];
            LDSM4(ahi[0], ahi[1], ahi[2], ahi[3],
                  a_addr(QHI + hh * 16384, l, wid * 16, kb));
            LDSM4(alo[0], alo[1], alo[2], alo[3],
                  a_addr(QLO + hh * 16384, l, wid * 16, kb));
            #pragma unroll
            for (int nf = 0; nf < 4; nf++) {
                uint32_t bh0, bh1, bh2, bh3, bl0, bl1, bl2, bl3;
                LDSM4(bh0, bh1, bh2, bh3, b_addr(KHI + hh * 8192, l, nf * 16, kb));
                LDSM4(bl0, bl1, bl2, bl3, b_addr(KLO + hh * 8192, l, nf * 16, kb));
                MMA(s[2*nf],   ahi, bh0, bh1);
                MMA(s[2*nf],   ahi, bl0, bl1);
                MMA(s[2*nf],   alo, bh0, bh1);
                MMA(s[2*nf+1], ahi, bh2, bh3);
                MMA(s[2*nf+1], ahi, bl2, bl3);
                MMA(s[2*nf+1], alo, bh2, bh3);
            }
        }

        if (jb >= 2 * qb) {
            int rbase = qb * 128 + wid * 16 + (l >> 2);
            int cbase = jb * 64 + (l & 3) * 2;
            #pragma unroll
            for (int f = 0; f < 8; f++) {
                int c0 = cbase + f * 8;
                if (c0     > rbase)     s[f][0] = -1e30f;
                if (c0 + 1 > rbase)     s[f][1] = -1e30f;
                if (c0     > rbase + 8) s[f][2] = -1e30f;
                if (c0 + 1 > rbase + 8) s[f][3] = -1e30f;
            }
        }

        float rmA = -1e30f, rmB = -1e30f;
        #pragma unroll
        for (int f = 0; f < 8; f++) {
            rmA = fmaxf(rmA, fmaxf(s[f][0], s[f][1]));
            rmB = fmaxf(rmB, fmaxf(s[f][2], s[f][3]));
        }
        rmA = fmaxf(rmA, __shfl_xor_sync(0xffffffffu, rmA, 1));
        rmA = fmaxf(rmA, __shfl_xor_sync(0xffffffffu, rmA, 2));
        rmB = fmaxf(rmB, __shfl_xor_sync(0xffffffffu, rmB, 1));
        rmB = fmaxf(rmB, __shfl_xor_sync(0xffffffffu, rmB, 2));
        float mnA = fmaxf(mA, rmA), mnB = fmaxf(mB, rmB);
        float aA = __expf(mA - mnA), aB = __expf(mB - mnB);
        float sumA = 0.f, sumB = 0.f;
        #pragma unroll
        for (int f = 0; f < 8; f++) {
            s[f][0] = __expf(s[f][0] - mnA);
            s[f][1] = __expf(s[f][1] - mnA);
            s[f][2] = __expf(s[f][2] - mnB);
            s[f][3] = __expf(s[f][3] - mnB);
            sumA += s[f][0] + s[f][1];
            sumB += s[f][2] + s[f][3];
        }
        sumA += __shfl_xor_sync(0xffffffffu, sumA, 1);
        sumA += __shfl_xor_sync(0xffffffffu, sumA, 2);
        sumB += __shfl_xor_sync(0xffffffffu, sumB, 1);
        sumB += __shfl_xor_sync(0xffffffffu, sumB, 2);
        lA = lA * aA + sumA; mA = mnA;
        lB = lB * aB + sumB; mB = mnB;
        #pragma unroll
        for (int f = 0; f < 16; f++) {
            o_acc[f][0] *= aA; o_acc[f][1] *= aA;
            o_acc[f][2] *= aB; o_acc[f][3] *= aB;
        }

        uint32_t ph[4][4], pl[4][4];
        #pragma unroll
        for (int kk = 0; kk < 4; kk++) {
            int f0 = 2 * kk, f1 = 2 * kk + 1;
            ph[kk][0] = packbf(s[f0][0], s[f0][1]);
            ph[kk][1] = packbf(s[f0][2], s[f0][3]);
            ph[kk][2] = packbf(s[f1][0], s[f1][1]);
            ph[kk][3] = packbf(s[f1][2], s[f1][3]);
            pl[kk][0] = packbf(bfres(s[f0][0]), bfres(s[f0][1]));
            pl[kk][1] = packbf(bfres(s[f0][2]), bfres(s[f0][3]));
            pl[kk][2] = packbf(bfres(s[f1][0]), bfres(s[f1][1]));
            pl[kk][3] = packbf(bfres(s[f1][2]), bfres(s[f1][3]));
        }

        #pragma unroll
        for (int kk = 0; kk < 4; kk++) {
            int kb = kk * 32;
            #pragma unroll
            for (int nf = 0; nf < 8; nf++) {
                uint32_t vh0, vh1, vh2, vh3, vl0, vl1, vl2, vl3;
                LDSM4(vh0, vh1, vh2, vh3, b_addr(VHI, l, nf * 16, kb));
                LDSM4(vl0, vl1, vl2, vl3, b_addr(VLO, l, nf * 16, kb));
                MMA(o_acc[2*nf],   ph[kk], vh0, vh1);
                MMA(o_acc[2*nf],   ph[kk], vl0, vl1);
                MMA(o_acc[2*nf],   pl[kk], vh0, vh1);
                MMA(o_acc[2*nf+1], ph[kk], vh2, vh3);
                MMA(o_acc[2*nf+1], ph[kk], vl2, vl3);
                MMA(o_acc[2*nf+1], pl[kk], vh2, vh3);
            }
        }
        __syncthreads();
    }

    float iA = 1.f / lA, iB = 1.f / lB;
    size_t rowA = (size_t)b * Tv + qb * 128 + wid * 16 + (l >> 2);
    size_t rowB = rowA + 8;
    #pragma unroll
    for (int f = 0; f < 16; f++) {
        int h = f * 8 + (l & 3) * 2;
        *(float2*)&out[rowA * Hv + h] = make_float2(o_acc[f][0] * iA, o_acc[f][1] * iA);
        *(float2*)&out[rowB * Hv + h] = make_float2(o_acc[f][2] * iB, o_acc[f][3] * iB);
    }
}

extern "C" void kernel_launch(void* const* d_in, const int* in_sizes, int n_in,
                              void* d_out, int out_size)
{
    const float* x  = (const float*)d_in[0];
    const float* Wq = (const float*)d_in[1];
    const float* Wk = (const float*)d_in[2];
    const float* Wv = (const float*)d_in[3];
    float* out = (float*)d_out;

    convert_w<<<(3 * Cv * Hv) / 256, 256>>>(Wq, Wk, Wv);

    cudaFuncSetAttribute(proj_mma,
                         cudaFuncAttributeMaxDynamicSharedMemorySize, PROJ_SMEM);
    proj_mma<<<dim3(Mv / 128, 3), 256, PROJ_SMEM>>>(x);

    cudaFuncSetAttribute(attn_mma,
                         cudaFuncAttributeMaxDynamicSharedMemorySize, ATTN_SMEM);
    attn_mma<<<dim3(32, Bv), 256, ATTN_SMEM>>>(out);
}